// round 3
// baseline (speedup 1.0000x reference)
#include <cuda_runtime.h>
#include <cuda_bf16.h>

// Piecewise-linear log-sigmoid approximation (table interp), GB300 sm_103a.
// vals: [64,2048,2048] fp32, x/y: 65-entry uniform tables.
//   x[i] = -10 + i*0.3125 (step 5/16, exact in fp32)
//   idx  = clamp((int)(v*3.2 + 32), 0, 63)
//   out  = v                          if v <  x[0]
//          0                          if v >= x[64]
//          y[i] + (v - x[i])*slope[i] otherwise
//
// R2: conflict-free per-lane replicated tables (bank l for lane l),
//     int32 indexing, no in-loop bounds checks (tail kernel handles rem),
//     8 float4/thread, streaming cache hints. Target ~290us (HBM wall).

#define NBP 65
#define NSEG 64
#define THREADS 256
#define V4_PER_THREAD 8   // float4s per thread

__global__ __launch_bounds__(THREADS)
void logsig_pwl_kernel(const float4* __restrict__ in4,
                       const float*  __restrict__ xt,
                       const float*  __restrict__ yt,
                       float4* __restrict__ out4)
{
    // s_tab[0      .. 2047]: y_lo replicated per-lane: [idx*32 + lane]
    // s_tab[2048 .. 4095]: slope replicated per-lane
    __shared__ float s_tab[2 * NSEG * 32];
    __shared__ float2 s_seg0[NSEG];       // staging: (y_lo, slope)
    __shared__ float  s_bounds[2];

    const int tid  = threadIdx.x;
    const int lane = tid & 31;

    if (tid < NSEG) {
        float xl = xt[tid], xh = xt[tid + 1];
        float yl = yt[tid], yh = yt[tid + 1];
        s_seg0[tid] = make_float2(yl, (yh - yl) / (xh - xl));
    }
    if (tid == 0) { s_bounds[0] = xt[0]; s_bounds[1] = xt[NBP - 1]; }
    __syncthreads();

    // Replicate 32x: entry e = idx*32 + l
    #pragma unroll
    for (int e = tid; e < NSEG * 32; e += THREADS) {
        float2 seg = s_seg0[e >> 5];
        s_tab[e] = seg.x;
        s_tab[e + NSEG * 32] = seg.y;
    }
    __syncthreads();

    const float x_lo_bound = s_bounds[0];   // -10
    const float x_hi_bound = s_bounds[1];   // +10
    const float INV_H = 3.2f;
    const float OFFS  = 32.0f;
    const float H     = 0.3125f;            // 5/16, exact
    const float X0    = -10.0f;

    // Exact-tile addressing: grid guarantees all accesses in range.
    unsigned base = blockIdx.x * (THREADS * V4_PER_THREAD) + tid;

    float4 v[V4_PER_THREAD];
    #pragma unroll
    for (int j = 0; j < V4_PER_THREAD; j++)
        v[j] = __ldcs(&in4[base + j * THREADS]);

    const float* tab_l = s_tab + lane;      // lane-private bank stripe

    #pragma unroll
    for (int j = 0; j < V4_PER_THREAD; j++) {
        float vv[4] = {v[j].x, v[j].y, v[j].z, v[j].w};
        float r[4];
        #pragma unroll
        for (int k = 0; k < 4; k++) {
            float val = vv[k];
            int idx = (int)fmaf(val, INV_H, OFFS);
            idx = max(0, min(idx, NSEG - 1));
            int a = idx << 5;
            float yl = tab_l[a];                    // bank==lane, conflict-free
            float m  = tab_l[a + NSEG * 32];        // bank==lane, conflict-free
            float x_lo = fmaf((float)idx, H, X0);   // exact, matches xt[idx]
            float interp = fmaf(val - x_lo, m, yl);
            r[k] = (val <  x_lo_bound) ? val
                 : (val >= x_hi_bound) ? 0.0f
                 : interp;
        }
        float4 o; o.x = r[0]; o.y = r[1]; o.z = r[2]; o.w = r[3];
        __stcs(&out4[base + j * THREADS], o);
    }
}

// Tail kernel: scalar, handles [start, n) elements.
__global__ void logsig_pwl_tail(const float* __restrict__ vals,
                                const float* __restrict__ xt,
                                const float* __restrict__ yt,
                                float* __restrict__ out,
                                long long start, long long n)
{
    long long i = start + (long long)blockIdx.x * blockDim.x + threadIdx.x;
    if (i >= n) return;
    float x0 = xt[0];
    float xK = xt[NBP - 1];
    float val = vals[i];
    int idx = (int)fmaf(val, 3.2f, 32.0f);
    idx = max(0, min(idx, NSEG - 1));
    float x_lo = xt[idx];
    float y_lo = yt[idx];
    float slope = (yt[idx + 1] - y_lo) / (xt[idx + 1] - x_lo);
    float interp = fmaf(val - x_lo, slope, y_lo);
    out[i] = (val < x0) ? val : (val >= xK) ? 0.0f : interp;
}

extern "C" void kernel_launch(void* const* d_in, const int* in_sizes, int n_in,
                              void* d_out, int out_size)
{
    const float* vals = (const float*)d_in[0];
    const float* xt   = (const float*)d_in[1];
    const float* yt   = (const float*)d_in[2];
    float* out        = (float*)d_out;

    long long n  = (long long)in_sizes[0];
    long long n4 = n / 4;

    const long long perBlock = (long long)THREADS * V4_PER_THREAD;   // 2048 float4s
    long long fullBlocks = n4 / perBlock;
    long long covered = fullBlocks * perBlock * 4;   // elements handled by main kernel

    if (fullBlocks > 0) {
        logsig_pwl_kernel<<<(unsigned)fullBlocks, THREADS>>>(
            (const float4*)vals, xt, yt, (float4*)out);
    }
    if (covered < n) {
        long long rem = n - covered;
        int tblocks = (int)((rem + 255) / 256);
        logsig_pwl_tail<<<tblocks, 256>>>(vals, xt, yt, out, covered, n);
    }
}